// round 9
// baseline (speedup 1.0000x reference)
#include <cuda_runtime.h>
#include <cstdint>

#define BB 128          // batch
#define PP 1200         // feature dim
#define NPB (BB * PP)   // 153600
#define MAXCH 16        // max p-chunks per iteration

// Static scratch (ping-pong everything to avoid same-launch read/write races)
__device__ float g_hA[NPB];               // h state buffer A
__device__ float g_hB[NPB];               // h state buffer B
__device__ float g_C0[NPB];               // frozen-contribution cache buffers
__device__ float g_C1[NPB];
__device__ float g_pA[MAXCH * NPB];       // partial sums ping
__device__ float g_pB[MAXCH * NPB];       // partial sums pong

__device__ __forceinline__ float f_p(float x) {
    float t = fminf(fmaxf(x, -1.0f), 1.0f);
    return t > 0.0f ? t : 0.01f * t;
}

// streaming (.cs, evict-first) and caching (.ca, default-evict) load variants
struct U64x2 { unsigned long long a, b; };
__device__ __forceinline__ U64x2 ldg_cs_128(const void* p) {
    U64x2 r;
    asm("ld.global.cs.v2.u64 {%0,%1}, [%2];" : "=l"(r.a), "=l"(r.b) : "l"(p));
    return r;
}
__device__ __forceinline__ U64x2 ldg_ca_128(const void* p) {
    U64x2 r;
    asm("ld.global.ca.v2.u64 {%0,%1}, [%2];" : "=l"(r.a), "=l"(r.b) : "l"(p));
    return r;
}
__device__ __forceinline__ unsigned long long ldg_cs_64(const void* p) {
    unsigned long long r;
    asm("ld.global.cs.u64 %0, [%1];" : "=l"(r) : "l"(p));
    return r;
}
__device__ __forceinline__ unsigned long long ldg_ca_64(const void* p) {
    unsigned long long r;
    asm("ld.global.ca.u64 %0, [%1];" : "=l"(r) : "l"(p));
    return r;
}

// Packed dual-fp32 FMA: acc = m * hp + acc   (Blackwell f32x2 pipe)
#define FMA2(acc, m, hp) \
    asm("fma.rn.f32x2 %0, %1, %2, %0;" : "+l"(acc) : "l"(m), "l"(hp))

// ---------------------------------------------------------------------------
// mainloop: partial_out[ch][b][q0..q0+QPT-1] = sum_{p in chunk} hd[p]*M[b,p,q]
// QPT = q floats per thread (4 -> LDG.128/p, 2 -> LDG.64/p)
// CA  = keep lines in L2 (q<240 column band reused by later iterations)
// ---------------------------------------------------------------------------
template<int PC, int QPT, bool CA>
__device__ __forceinline__ void mainloopA(
    const float* __restrict__ M, const float2* hd, float* __restrict__ pout,
    int ch, int b, int q0)
{
    const char* base = (const char*)(M + (size_t)b * PP * PP
                                       + (size_t)(ch * PC) * PP + q0);
    if (QPT == 4) {
        unsigned long long acc0 = 0, acc1 = 0;
        #pragma unroll 8
        for (int p = 0; p < PC; ++p) {
            unsigned long long hp = *reinterpret_cast<const unsigned long long*>(&hd[p]);
            U64x2 m = CA ? ldg_ca_128(base + (size_t)p * (PP * 4))
                         : ldg_cs_128(base + (size_t)p * (PP * 4));
            FMA2(acc0, m.a, hp);
            FMA2(acc1, m.b, hp);
        }
        unsigned long long* out = reinterpret_cast<unsigned long long*>(
            pout + ((size_t)ch * BB + b) * PP + q0);
        out[0] = acc0;
        out[1] = acc1;
    } else {
        unsigned long long acc0 = 0;
        #pragma unroll 8
        for (int p = 0; p < PC; ++p) {
            unsigned long long hp = *reinterpret_cast<const unsigned long long*>(&hd[p]);
            unsigned long long m = CA ? ldg_ca_64(base + (size_t)p * (PP * 4))
                                      : ldg_cs_64(base + (size_t)p * (PP * 4));
            FMA2(acc0, m, hp);
        }
        *reinterpret_cast<unsigned long long*>(
            pout + ((size_t)ch * BB + b) * PP + q0) = acc0;
    }
}

// ---------------------------------------------------------------------------
// iter-0 phase A: h = f_p(query); partials(0) -> pA
// Marks the (p<960, q<240) band .ca so F1 hits L2 on it.
// ---------------------------------------------------------------------------
template<int PC>
__global__ void phaseA0(const float* __restrict__ M, const float* __restrict__ query)
{
    const int ch = blockIdx.x, b = blockIdx.y, tid = threadIdx.x;
    __shared__ float2 hd[PC];
    if (tid < PC) {
        float v = f_p(query[b * PP + ch * PC + tid]);
        hd[tid] = make_float2(v, v);
    }
    __syncthreads();
    const int q0 = blockIdx.z * (blockDim.x * 4) + tid * 4;
    if (q0 >= PP) return;
    if (ch < 8 && q0 < 240) mainloopA<PC, 4, true >(M, hd, g_pA, ch, b, q0);
    else                    mainloopA<PC, 4, false>(M, hd, g_pA, ch, b, q0);
}

// ---------------------------------------------------------------------------
// fused kernel F_t:
//   prologue: h_t[window] = f_p(h_{t-1}*(0.8 + C_in + sum partials_in));
//             z==0 block persists h_t (q<QLO) or writes the just-frozen
//             output slice q in [QLO, window_end) straight to d_out, and
//             folds newly-frozen chunks into C_out.
//   mainloop: partials_t[own chunk] over q < n_on -> partials_out, with the
//             (ch<CHLIM, q<240) band loaded .ca for L2 reuse downstream.
// ---------------------------------------------------------------------------
template<int PC, int QPT, int NCHP, int NACTP,
         bool READC, bool WRITEC, bool FIRSTW, bool IT0P, int QLO, int CHLIM>
__global__ void phaseF(const float* __restrict__ M,
                       const float* __restrict__ hin, float* __restrict__ hout,
                       const float* __restrict__ Cin, float* __restrict__ Cout,
                       const float* __restrict__ pin, float* __restrict__ pout,
                       float* __restrict__ outF, int n_on)
{
    const int ch = blockIdx.x, b = blockIdx.y, tid = threadIdx.x;
    const int pbase = ch * PC;
    __shared__ float2 hd[PC];

    if (tid < PC) {
        const int q  = pbase + tid;
        const int gi = b * PP + q;
        float h = hin[gi];
        if (IT0P) h = f_p(h);

        float sa = 0.0f, sf = 0.0f;
        const float* pp = pin + (size_t)b * PP + q;
        #pragma unroll
        for (int s = 0; s < NCHP; ++s) {
            float v = pp[(size_t)s * NPB];
            if (s < NACTP) sa += v; else sf += v;
        }
        float c = READC ? Cin[gi] : 0.0f;
        float hnew = f_p(h * (0.8f + sa + sf + c));
        hd[tid] = make_float2(hnew, hnew);

        if (blockIdx.z == 0) {
            if (q >= QLO) {
                outF[gi] = hnew;                 // just-frozen final slice
            } else {
                hout[gi] = hnew;
                if (WRITEC) Cout[gi] = FIRSTW ? sf : (c + sf);
            }
        }
    }
    __syncthreads();

    const int q0 = blockIdx.z * (blockDim.x * QPT) + tid * QPT;
    if (q0 >= n_on) return;
    if (CHLIM > 0 && ch < CHLIM && q0 < 240)
        mainloopA<PC, QPT, true >(M, hd, pout, ch, b, q0);
    else
        mainloopA<PC, QPT, false>(M, hd, pout, ch, b, q0);
}

// ---------------------------------------------------------------------------
// final update (q<240 only; frozen slices already written by F prologues):
// out[q<240] = f_p(hB*(0.8 + C0 + sum of 16 chunks of pA))
// ---------------------------------------------------------------------------
__global__ void phaseBfinal(float4* __restrict__ out)
{
    int i4 = blockIdx.x * blockDim.x + threadIdx.x;   // over BB*60 groups
    if (i4 >= BB * 60) return;
    int b = i4 / 60, r = i4 % 60;
    int q = r * 4;
    int gi4 = (b * PP + q) / 4;

    float4 s = make_float4(0.f, 0.f, 0.f, 0.f);
    const float* pp = g_pA + (size_t)b * PP + q;
    #pragma unroll
    for (int sI = 0; sI < 16; ++sI) {
        float4 v = *reinterpret_cast<const float4*>(pp + (size_t)sI * NPB);
        s.x += v.x; s.y += v.y; s.z += v.z; s.w += v.w;
    }

    float4 h = reinterpret_cast<const float4*>(g_hB)[gi4];
    float4 c = reinterpret_cast<const float4*>(g_C0)[gi4];
    float4 o;
    o.x = f_p(h.x * (0.8f + s.x + c.x));
    o.y = f_p(h.y * (0.8f + s.y + c.y));
    o.z = f_p(h.z * (0.8f + s.z + c.z));
    o.w = f_p(h.w * (0.8f + s.w + c.w));
    out[gi4] = o;
}

// ---------------------------------------------------------------------------
extern "C" void kernel_launch(void* const* d_in, const int* in_sizes, int n_in,
                              void* d_out, int out_size)
{
    const float* query = (const float*)d_in[0];
    const float* M     = (const float*)d_in[1];
    float*       out   = (float*)d_out;

    float *hA, *hB, *C0, *C1, *pA, *pB;
    cudaGetSymbolAddress((void**)&hA, g_hA);
    cudaGetSymbolAddress((void**)&hB, g_hB);
    cudaGetSymbolAddress((void**)&C0, g_C0);
    cudaGetSymbolAddress((void**)&C1, g_C1);
    cudaGetSymbolAddress((void**)&pA, g_pA);
    cudaGetSymbolAddress((void**)&pB, g_pB);

    // Plan (step t updates q<non_t, mainloop covers p<non_{t-1}):
    //  launch : pc qpt  p-range q-range prologue(NCHP,NACTP) h        C       part    .ca band
    //  A0     : 120  4  <1200   <1200   -                    query    -       ->pA    p<960,q<240
    //  F1     : 120  4  <1200   <960    (10,10) noC, out[960,1200)  q->hA  -  pA->pB  p<960,q<240
    //  F2     : 120  4  <960    <720    (10, 8) wC0 first, out[720,960) hA->hB ->C0 pB->pA  p<720,q<240
    //  F3     :  60  2  <720    <480    ( 8, 6) rC0 wC1, out[480,720)  hB->hA C0->C1 pA->pB p<480,q<240
    //  F4     :  30  2  <480    <240    (12, 8) rC1 wC0, out[240,480)  hA->hB C1->C0 pB->pA -
    //  Bfinal : out[q<240] from hB, C0, pA(16 chunks)

    phaseA0<120><<<dim3(10, BB, 3), 128>>>(M, query);

    phaseF<120, 4, 10, 10, false, false, false, true,  960, 8>
        <<<dim3(10, BB, 2), 128>>>(M, query, hA, C0, C1, pA, pB, out, 960);

    phaseF<120, 4, 10,  8, false, true,  true,  false, 720, 6>
        <<<dim3( 8, BB, 2), 128>>>(M, hA, hB, C1, C0, pB, pA, out, 720);

    phaseF< 60, 2,  8,  6, true,  true,  false, false, 480, 8>
        <<<dim3(12, BB, 1), 256>>>(M, hB, hA, C0, C1, pA, pB, out, 480);

    phaseF< 30, 2, 12,  8, true,  true,  false, false, 240, 0>
        <<<dim3(16, BB, 1), 128>>>(M, hA, hB, C1, C0, pB, pA, out, 240);

    phaseBfinal<<<30, 256>>>((float4*)out);
}

// round 10
// speedup vs baseline: 1.0959x; 1.0959x over previous
#include <cuda_runtime.h>
#include <cstdint>

#define BB 128          // batch
#define PP 1200         // feature dim
#define NPB (BB * PP)   // 153600
#define MAXCH 12        // max p-chunks per iteration

// Static scratch (ping-pong everything to avoid same-launch read/write races)
__device__ float g_hA[NPB];               // h state buffer A
__device__ float g_hB[NPB];               // h state buffer B
__device__ float g_C0[NPB];               // frozen-contribution cache buffers
__device__ float g_C1[NPB];
__device__ float g_pA[MAXCH * NPB];       // partial sums ping
__device__ float g_pB[MAXCH * NPB];       // partial sums pong

__device__ __forceinline__ float f_p(float x) {
    float t = fminf(fmaxf(x, -1.0f), 1.0f);
    return t > 0.0f ? t : 0.01f * t;
}

// streaming loads (.cs evict-first; M is single-use per launch)
struct U64x2 { unsigned long long a, b; };
__device__ __forceinline__ U64x2 ldg_cs_128(const void* p) {
    U64x2 r;
    asm("ld.global.cs.v2.u64 {%0,%1}, [%2];" : "=l"(r.a), "=l"(r.b) : "l"(p));
    return r;
}
__device__ __forceinline__ unsigned long long ldg_cs_64(const void* p) {
    unsigned long long r;
    asm("ld.global.cs.u64 %0, [%1];" : "=l"(r) : "l"(p));
    return r;
}

// Packed dual-fp32 FMA: acc = m * hp + acc   (Blackwell f32x2 pipe)
#define FMA2(acc, m, hp) \
    asm("fma.rn.f32x2 %0, %1, %2, %0;" : "+l"(acc) : "l"(m), "l"(hp))

// ---------------------------------------------------------------------------
// mainloop: partial_out[ch][b][q0..q0+QPT-1] = sum_{p in chunk} hd[p]*M[b,p,q]
// QPT = q floats per thread (4 -> LDG.128/p, 2 -> LDG.64/p)
// ---------------------------------------------------------------------------
template<int PC, int QPT>
__device__ __forceinline__ void mainloopA(
    const float* __restrict__ M, const float2* hd, float* __restrict__ pout,
    int ch, int b, int q0)
{
    const char* base = (const char*)(M + (size_t)b * PP * PP
                                       + (size_t)(ch * PC) * PP + q0);
    if (QPT == 4) {
        unsigned long long acc0 = 0, acc1 = 0;
        #pragma unroll 8
        for (int p = 0; p < PC; ++p) {
            unsigned long long hp = *reinterpret_cast<const unsigned long long*>(&hd[p]);
            U64x2 m = ldg_cs_128(base + (size_t)p * (PP * 4));
            FMA2(acc0, m.a, hp);
            FMA2(acc1, m.b, hp);
        }
        unsigned long long* out = reinterpret_cast<unsigned long long*>(
            pout + ((size_t)ch * BB + b) * PP + q0);
        out[0] = acc0;
        out[1] = acc1;
    } else {
        unsigned long long acc0 = 0;
        #pragma unroll 8
        for (int p = 0; p < PC; ++p) {
            unsigned long long hp = *reinterpret_cast<const unsigned long long*>(&hd[p]);
            unsigned long long m = ldg_cs_64(base + (size_t)p * (PP * 4));
            FMA2(acc0, m, hp);
        }
        *reinterpret_cast<unsigned long long*>(
            pout + ((size_t)ch * BB + b) * PP + q0) = acc0;
    }
}

// ---------------------------------------------------------------------------
// iter-0 phase A: h = f_p(query); partials(0) -> pA
// ---------------------------------------------------------------------------
template<int PC>
__global__ void phaseA0(const float* __restrict__ M, const float* __restrict__ query)
{
    const int ch = blockIdx.x, b = blockIdx.y, tid = threadIdx.x;
    __shared__ float2 hd[PC];
    if (tid < PC) {
        float v = f_p(query[b * PP + ch * PC + tid]);
        hd[tid] = make_float2(v, v);
    }
    __syncthreads();
    const int q0 = blockIdx.z * (blockDim.x * 4) + tid * 4;
    if (q0 >= PP) return;
    mainloopA<PC, 4>(M, hd, g_pA, ch, b, q0);
}

// ---------------------------------------------------------------------------
// fused kernel F_t (PDL secondary: grid-dependency sync before any dependent
// global read):
//   prologue: h_t[window] = f_p(h_{t-1}*(0.8 + C_in + sum partials_in));
//             z==0 block persists h_t (q<QLO) or writes the just-frozen
//             output slice q in [QLO, window_end) straight to d_out, and
//             folds newly-frozen chunks into C_out.
//   mainloop: partials_t[own chunk] over q < n_on -> partials_out.
// Buffer ping-pong across launches removes all same-launch races.
// ---------------------------------------------------------------------------
template<int PC, int QPT, int NCHP, int NACTP,
         bool READC, bool WRITEC, bool FIRSTW, bool IT0P, int QLO>
__global__ void phaseF(const float* __restrict__ M,
                       const float* __restrict__ hin, float* __restrict__ hout,
                       const float* __restrict__ Cin, float* __restrict__ Cout,
                       const float* __restrict__ pin, float* __restrict__ pout,
                       float* __restrict__ outF, int n_on)
{
#if __CUDA_ARCH__ >= 900
    cudaGridDependencySynchronize();
#endif
    const int ch = blockIdx.x, b = blockIdx.y, tid = threadIdx.x;
    const int pbase = ch * PC;
    __shared__ float2 hd[PC];

    if (tid < PC) {
        const int q  = pbase + tid;
        const int gi = b * PP + q;
        float h = hin[gi];
        if (IT0P) h = f_p(h);

        float sa = 0.0f, sf = 0.0f;
        const float* pp = pin + (size_t)b * PP + q;
        #pragma unroll
        for (int s = 0; s < NCHP; ++s) {
            float v = pp[(size_t)s * NPB];
            if (s < NACTP) sa += v; else sf += v;
        }
        float c = READC ? Cin[gi] : 0.0f;
        float hnew = f_p(h * (0.8f + sa + sf + c));
        hd[tid] = make_float2(hnew, hnew);

        if (blockIdx.z == 0) {
            if (q >= QLO) {
                outF[gi] = hnew;                 // just-frozen final slice
            } else {
                hout[gi] = hnew;
                if (WRITEC) Cout[gi] = FIRSTW ? sf : (c + sf);
            }
        }
    }
    __syncthreads();

    const int q0 = blockIdx.z * (blockDim.x * QPT) + tid * QPT;
    if (q0 >= n_on) return;
    mainloopA<PC, QPT>(M, hd, pout, ch, b, q0);
}

// ---------------------------------------------------------------------------
// final update (q<240 only; frozen slices already written by F prologues):
// out[q<240] = f_p(hB*(0.8 + C0 + sum of 8 chunks of pA))
// ---------------------------------------------------------------------------
__global__ void phaseBfinal(float4* __restrict__ out)
{
#if __CUDA_ARCH__ >= 900
    cudaGridDependencySynchronize();
#endif
    int i4 = blockIdx.x * blockDim.x + threadIdx.x;   // over BB*60 groups
    if (i4 >= BB * 60) return;
    int b = i4 / 60, r = i4 % 60;
    int q = r * 4;
    int gi4 = (b * PP + q) / 4;

    float4 s = make_float4(0.f, 0.f, 0.f, 0.f);
    const float* pp = g_pA + (size_t)b * PP + q;
    #pragma unroll
    for (int sI = 0; sI < 8; ++sI) {
        float4 v = *reinterpret_cast<const float4*>(pp + (size_t)sI * NPB);
        s.x += v.x; s.y += v.y; s.z += v.z; s.w += v.w;
    }

    float4 h = reinterpret_cast<const float4*>(g_hB)[gi4];
    float4 c = reinterpret_cast<const float4*>(g_C0)[gi4];
    float4 o;
    o.x = f_p(h.x * (0.8f + s.x + c.x));
    o.y = f_p(h.y * (0.8f + s.y + c.y));
    o.z = f_p(h.z * (0.8f + s.z + c.z));
    o.w = f_p(h.w * (0.8f + s.w + c.w));
    out[gi4] = o;
}

// ---------------------------------------------------------------------------
// helper: launch with programmatic stream serialization (PDL)
// ---------------------------------------------------------------------------
template<typename K, typename... Args>
static void launch_pdl(dim3 grid, dim3 block, K kernel, Args... args)
{
    cudaLaunchConfig_t cfg = {};
    cfg.gridDim  = grid;
    cfg.blockDim = block;
    cudaLaunchAttribute attr[1];
    attr[0].id = cudaLaunchAttributeProgrammaticStreamSerialization;
    attr[0].val.programmaticStreamSerializationAllowed = 1;
    cfg.attrs = attr;
    cfg.numAttrs = 1;
    cudaLaunchKernelEx(&cfg, kernel, args...);
}

// ---------------------------------------------------------------------------
extern "C" void kernel_launch(void* const* d_in, const int* in_sizes, int n_in,
                              void* d_out, int out_size)
{
    const float* query = (const float*)d_in[0];
    const float* M     = (const float*)d_in[1];
    float*       out   = (float*)d_out;

    float *hA, *hB, *C0, *C1, *pA, *pB;
    cudaGetSymbolAddress((void**)&hA, g_hA);
    cudaGetSymbolAddress((void**)&hB, g_hB);
    cudaGetSymbolAddress((void**)&C0, g_C0);
    cudaGetSymbolAddress((void**)&C1, g_C1);
    cudaGetSymbolAddress((void**)&pA, g_pA);
    cudaGetSymbolAddress((void**)&pB, g_pB);

    // Plan (step t updates q<non_t, mainloop covers p<non_{t-1}):
    //  launch : pc qpt nch  p-range  q-range  prologue(NCHP,NACTP)           h         C        partials
    //  A0     : 120  4  10  <1200    <1200    -                              query     -        ->pA
    //  F1     : 120  4  10  <1200    <960     (10,10) noC, out[960,1200)     query->hA -        pA->pB
    //  F2     : 120  4   8  <960     <720     (10, 8) wC0 first, out[720,960) hA->hB   ->C0     pB->pA
    //  F3     :  60  2  12  <720     <480     ( 8, 6) rC0 wC1, out[480,720)  hB->hA    C0->C1   pA->pB
    //  F4     :  60  2   8  <480     <240     (12, 8) rC1 wC0, out[240,480)  hA->hB    C1->C0   pB->pA
    //  Bfinal : out[q<240] from hB, C0, pA(8 chunks)

    phaseA0<120><<<dim3(10, BB, 3), 128>>>(M, query);

    launch_pdl(dim3(10, BB, 2), dim3(128),
               phaseF<120, 4, 10, 10, false, false, false, true,  960>,
               M, query, hA, (const float*)C0, C1, (const float*)pA, pB, out, 960);

    launch_pdl(dim3( 8, BB, 2), dim3(128),
               phaseF<120, 4, 10,  8, false, true,  true,  false, 720>,
               M, (const float*)hA, hB, (const float*)C1, C0,
               (const float*)pB, pA, out, 720);

    launch_pdl(dim3(12, BB, 1), dim3(256),
               phaseF< 60, 2,  8,  6, true,  true,  false, false, 480>,
               M, (const float*)hB, hA, (const float*)C0, C1,
               (const float*)pA, pB, out, 480);

    launch_pdl(dim3( 8, BB, 1), dim3(128),
               phaseF< 60, 2, 12,  8, true,  true,  false, false, 240>,
               M, (const float*)hA, hB, (const float*)C1, C0,
               (const float*)pB, pA, out, 240);

    launch_pdl(dim3(30), dim3(256), phaseBfinal, (float4*)out);
}